// round 8
// baseline (speedup 1.0000x reference)
#include <cuda_runtime.h>
#include <cuda_bf16.h>
#include <cstdint>

// Problem constants
#define BB    16
#define SS    4
#define HID   4096
#define HH    32
#define KVH   8
#define DD    128
#define T0    4092      // START_POS
#define TT    4096
#define M64   64        // B*S rows
#define SCALE 0.08838834764831845f  // 1/sqrt(128)

#define OUT_ELEMS  (M64*HID)
#define KNEW_OFF   OUT_ELEMS
#define VNEW_OFF   (OUT_ELEMS + BB*KVH*SS*DD)

#define NSPLIT 8                 // key splits per (b,kv)
#define NPART  (BB*KVH*NSPLIT)   // 1024 block partials

// ---------------- scratch ----------------
__device__ float g_qproj[M64*HID];
__device__ float g_kproj[M64*KVH*DD];
__device__ float g_vproj[M64*KVH*DD];
__device__ float g_q[BB*KVH*16*DD];       // [bg][row16][d], rope'd, *SCALE
__device__ float g_part_acc[NPART*16*DD];
__device__ float g_part_m[NPART*16];
__device__ float g_part_l[NPART*16];
__device__ float g_ao[M64*HID];

// ---------------- helpers ----------------
__device__ __forceinline__ unsigned f2tf32(float x) {
    unsigned r;
    asm("cvt.rna.tf32.f32 %0, %1;" : "=r"(r) : "f"(x));
    return r;
}
__device__ __forceinline__ void mma8(float d[4], const unsigned a[4], unsigned b0, unsigned b1) {
    asm volatile(
        "mma.sync.aligned.m16n8k8.row.col.f32.tf32.tf32.f32 "
        "{%0,%1,%2,%3}, {%4,%5,%6,%7}, {%8,%9}, {%0,%1,%2,%3};"
        : "+f"(d[0]), "+f"(d[1]), "+f"(d[2]), "+f"(d[3])
        : "r"(a[0]), "r"(a[1]), "r"(a[2]), "r"(a[3]), "r"(b0), "r"(b1));
}
__device__ __forceinline__ void cpa16(void* dst, const void* src) {
    unsigned d = (unsigned)__cvta_generic_to_shared(dst);
    asm volatile("cp.async.cg.shared.global [%0], [%1], 16;" :: "r"(d), "l"(src));
}
#define CPA_COMMIT() asm volatile("cp.async.commit_group;" ::: "memory")

// ================= GEMM: 64(M)x64(N) block tile, BK=32, 4-stage cp.async =============
#define GST 4
#define GSTRIDE 36
#define GSTAGE_F (64*GSTRIDE)
#define GEMM_SMEM (GST*GSTAGE_F*2*sizeof(float))   // 73728 B

__device__ __forceinline__ void gemm_body(
    const float* __restrict__ A, const float* __restrict__ W,
    const float* __restrict__ bias, float* __restrict__ C, int ldc, int n0, float* sm)
{
    float* As = sm;
    float* Ws = sm + GST * GSTAGE_F;
    const int t = threadIdx.x;
    const int wid = t >> 5, lane = t & 31;
    const int gl = lane >> 2, tg = lane & 3;
    const int mb = (wid >> 1) * 32, nb = (wid & 1) * 32;

    float acc[2][4][4];
#pragma unroll
    for (int a = 0; a < 2; a++)
#pragma unroll
        for (int b = 0; b < 4; b++)
#pragma unroll
            for (int c = 0; c < 4; c++) acc[a][b][c] = 0.f;

    auto stage = [&](int s, int k0) {
#pragma unroll
        for (int i = 0; i < 4; i++) {
            int f = t + i * 128;
            int row = f >> 3, c4 = (f & 7) * 4;
            cpa16(&As[s * GSTAGE_F + row * GSTRIDE + c4], A + (size_t)row * 4096 + k0 + c4);
            cpa16(&Ws[s * GSTAGE_F + row * GSTRIDE + c4], W + (size_t)(n0 + row) * 4096 + k0 + c4);
        }
        CPA_COMMIT();
    };

    stage(0, 0); stage(1, 32); stage(2, 64);

    for (int it = 0; it < 128; it++) {
        if (it < 126)       asm volatile("cp.async.wait_group 2;" ::: "memory");
        else if (it == 126) asm volatile("cp.async.wait_group 1;" ::: "memory");
        else                asm volatile("cp.async.wait_group 0;" ::: "memory");
        __syncthreads();
        if (it + 3 < 128) stage((it + 3) & 3, (it + 3) * 32);

        const float* as = As + (it & 3) * GSTAGE_F;
        const float* ws = Ws + (it & 3) * GSTAGE_F;
#pragma unroll
        for (int kk = 0; kk < 4; kk++) {
            unsigned a[2][4];
#pragma unroll
            for (int tt2 = 0; tt2 < 2; tt2++) {
                int r0 = mb + tt2 * 16 + gl;
                a[tt2][0] = f2tf32(as[r0 * GSTRIDE + kk * 8 + tg]);
                a[tt2][1] = f2tf32(as[(r0 + 8) * GSTRIDE + kk * 8 + tg]);
                a[tt2][2] = f2tf32(as[r0 * GSTRIDE + kk * 8 + tg + 4]);
                a[tt2][3] = f2tf32(as[(r0 + 8) * GSTRIDE + kk * 8 + tg + 4]);
            }
#pragma unroll
            for (int j = 0; j < 4; j++) {
                unsigned b0 = f2tf32(ws[(nb + j * 8 + gl) * GSTRIDE + kk * 8 + tg]);
                unsigned b1 = f2tf32(ws[(nb + j * 8 + gl) * GSTRIDE + kk * 8 + tg + 4]);
                mma8(acc[0][j], a[0], b0, b1);
                mma8(acc[1][j], a[1], b0, b1);
            }
        }
    }
#pragma unroll
    for (int tt2 = 0; tt2 < 2; tt2++)
#pragma unroll
        for (int j = 0; j < 4; j++) {
            int r0 = mb + tt2 * 16 + gl;
            int col = n0 + nb + j * 8 + 2 * tg;
            float b0v = 0.f, b1v = 0.f;
            if (bias) { b0v = bias[col]; b1v = bias[col + 1]; }
            C[(size_t)r0 * ldc + col]           = acc[tt2][j][0] + b0v;
            C[(size_t)r0 * ldc + col + 1]       = acc[tt2][j][1] + b1v;
            C[(size_t)(r0 + 8) * ldc + col]     = acc[tt2][j][2] + b0v;
            C[(size_t)(r0 + 8) * ldc + col + 1] = acc[tt2][j][3] + b1v;
        }
}

__global__ void __launch_bounds__(128) qkv_gemm(
    const float* __restrict__ A,
    const float* __restrict__ qw, const float* __restrict__ qb,
    const float* __restrict__ kw, const float* __restrict__ kb,
    const float* __restrict__ vw, const float* __restrict__ vb)
{
    extern __shared__ float gsm[];
    int blk = blockIdx.x;
    if (blk < 64)      gemm_body(A, qw, qb, g_qproj, 4096, blk * 64, gsm);
    else if (blk < 80) gemm_body(A, kw, kb, g_kproj, 1024, (blk - 64) * 64, gsm);
    else               gemm_body(A, vw, vb, g_vproj, 1024, (blk - 80) * 64, gsm);
}

__global__ void __launch_bounds__(128) o_gemm(const float* __restrict__ ow, float* __restrict__ out)
{
    extern __shared__ float gsm[];
    gemm_body(g_ao, ow, nullptr, out, 4096, blockIdx.x * 64, gsm);
}

// ---------------- RoPE + scatter (positions[b][s] == b*S+s) ----------------
__global__ void __launch_bounds__(256) rope_scatter(
    float* __restrict__ knew, float* __restrict__ vnew)
{
    int idx = blockIdx.x * 256 + threadIdx.x;
    const float NEG_LOG2_BASE_OVER_HALF = -13.287712379549449f / 64.f;
    if (idx < 131072) {                       // Q
        int d0 = idx & 63;
        int h  = (idx >> 6) & 31;
        int m  = idx >> 11;
        int b = m >> 2, s = m & 3;
        float ang = (float)m * exp2f((float)d0 * NEG_LOG2_BASE_OVER_HALF);
        float c = cosf(ang), sn = sinf(ang);
        float x1 = g_qproj[m * 4096 + h * 128 + d0];
        float x2 = g_qproj[m * 4096 + h * 128 + d0 + 64];
        int g = h >> 2, r = h & 3, row = r * 4 + s;
        int base = ((b * 8 + g) * 16 + row) * 128;
        g_q[base + d0]      = (x1 * c - x2 * sn) * SCALE;
        g_q[base + d0 + 64] = (x2 * c + x1 * sn) * SCALE;
    } else if (idx < 163840) {                // K
        int j = idx - 131072;
        int d0 = j & 63;
        int kv = (j >> 6) & 7;
        int m  = j >> 9;
        int b = m >> 2, s = m & 3;
        float ang = (float)m * exp2f((float)d0 * NEG_LOG2_BASE_OVER_HALF);
        float c = cosf(ang), sn = sinf(ang);
        float x1 = g_kproj[m * 1024 + kv * 128 + d0];
        float x2 = g_kproj[m * 1024 + kv * 128 + d0 + 64];
        int base = ((b * 8 + kv) * 4 + s) * 128;
        knew[base + d0]      = x1 * c - x2 * sn;
        knew[base + d0 + 64] = x2 * c + x1 * sn;
    } else if (idx < 229376) {                // V copy
        int j = idx - 163840;
        int d  = j & 127;
        int kv = (j >> 7) & 7;
        int m  = j >> 10;
        int b = m >> 2, s = m & 3;
        vnew[((b * 8 + kv) * 4 + s) * 128 + d] = g_vproj[m * 1024 + kv * 128 + d];
    }
}

// ================= Attention =================
// grid 1024: bg = blk>>3, sub = blk&7 -> keys [sub*512, sub*512+512), 16 tiles of 32.
// 4 warps; warp w covers tile keys [w*8, w*8+8). K/V separate cp.async groups.
#define NT 16
#define KROWK 132
#define VROWV 136
#define SMK_STAGE (32*KROWK)
#define SMV_STAGE (32*VROWV)
#define SMEM_ATTN ((2*SMK_STAGE + 2*SMV_STAGE) * sizeof(float))   // 68608 B

__global__ void __launch_bounds__(128, 2) attn2(
    const float* __restrict__ kc, const float* __restrict__ vc,
    const float* __restrict__ knew, const float* __restrict__ vnew)
{
    extern __shared__ float sm[];
    float* Ks = sm;                        // [2][32][132]
    float* Vs = sm + 2 * SMK_STAGE;        // [2][32][136]

    const int tid = threadIdx.x, wid = tid >> 5, lane = tid & 31;
    const int gl = lane >> 2, tg = lane & 3;
    const int bg = blockIdx.x >> 3, sub = blockIdx.x & 7;
    const int kbase = sub * 512;

    const float* kcb = kc + (size_t)bg * TT * DD;
    const float* vcb = vc + (size_t)bg * TT * DD;
    const float* knb = knew + (size_t)bg * SS * DD;
    const float* vnb = vnew + (size_t)bg * SS * DD;

    const float* q = g_q + (size_t)bg * 2048;
    unsigned aq[16][4];
#pragma unroll
    for (int kk = 0; kk < 16; kk++) {
        aq[kk][0] = f2tf32(q[gl * 128 + kk * 8 + tg]);
        aq[kk][1] = f2tf32(q[(gl + 8) * 128 + kk * 8 + tg]);
        aq[kk][2] = f2tf32(q[gl * 128 + kk * 8 + tg + 4]);
        aq[kk][3] = f2tf32(q[(gl + 8) * 128 + kk * 8 + tg + 4]);
    }

    float acc[16][4];
#pragma unroll
    for (int j = 0; j < 16; j++)
#pragma unroll
        for (int c = 0; c < 4; c++) acc[j][c] = 0.f;
    float m0 = -1e30f, m1 = -1e30f, l0 = 0.f, l1 = 0.f;

    auto stageK = [&](int buf, int tile) {
        int key0 = kbase + tile * 32;
        float* kd = Ks + buf * SMK_STAGE;
        if (key0 + 32 <= T0) {
            const char* ksrc = (const char*)(kcb + (size_t)key0 * DD);
#pragma unroll
            for (int i = 0; i < 8; i++) {
                int f = tid + i * 128;
                int row = f >> 5, c4 = (f & 31) * 4;
                cpa16(&kd[row * KROWK + c4], ksrc + (size_t)f * 16);
            }
        } else {
#pragma unroll
            for (int i = 0; i < 8; i++) {
                int f = tid + i * 128;
                int row = f >> 5, c4 = (f & 31) * 4;
                int t = key0 + row;
                const float* ks = (t < T0) ? (kcb + (size_t)t * DD + c4) : (knb + (size_t)(t - T0) * DD + c4);
                cpa16(&kd[row * KROWK + c4], ks);
            }
        }
        CPA_COMMIT();
    };
    auto stageV = [&](int buf, int tile) {
        int key0 = kbase + tile * 32;
        float* vd = Vs + buf * SMV_STAGE;
        if (key0 + 32 <= T0) {
            const char* vsrc = (const char*)(vcb + (size_t)key0 * DD);
#pragma unroll
            for (int i = 0; i < 8; i++) {
                int f = tid + i * 128;
                int row = f >> 5, c4 = (f & 31) * 4;
                cpa16(&vd[row * VROWV + c4], vsrc + (size_t)f * 16);
            }
        } else {
#pragma unroll
            for (int i = 0; i < 8; i++) {
                int f = tid + i * 128;
                int row = f >> 5, c4 = (f & 31) * 4;
                int t = key0 + row;
                const float* vs = (t < T0) ? (vcb + (size_t)t * DD + c4) : (vnb + (size_t)(t - T0) * DD + c4);
                cpa16(&vd[row * VROWV + c4], vs);
            }
        }
        CPA_COMMIT();
    };

    stageK(0, 0);
    stageV(0, 0);

#pragma unroll 1
    for (int tile = 0; tile < NT; tile++) {
        int buf = tile & 1;
        // wait for K_t (V_t may still be in flight)
        asm volatile("cp.async.wait_group 1;" ::: "memory");
        __syncthreads();   // also guarantees everyone finished reading buf^1 last iter
        if (tile + 1 < NT) {
            stageK(buf ^ 1, tile + 1);
            stageV(buf ^ 1, tile + 1);
        }

        // ---- QK^T: 2 independent mma chains ----
        const float* KT = Ks + buf * SMK_STAGE + wid * 8 * KROWK;
        float csA[4] = {0.f, 0.f, 0.f, 0.f};
        float csB[4] = {0.f, 0.f, 0.f, 0.f};
#pragma unroll
        for (int kk = 0; kk < 16; kk += 2) {
            unsigned b0 = f2tf32(KT[gl * KROWK + kk * 8 + tg]);
            unsigned b1 = f2tf32(KT[gl * KROWK + kk * 8 + tg + 4]);
            mma8(csA, aq[kk], b0, b1);
            unsigned c0 = f2tf32(KT[gl * KROWK + kk * 8 + 8 + tg]);
            unsigned c1 = f2tf32(KT[gl * KROWK + kk * 8 + 8 + tg + 4]);
            mma8(csB, aq[kk + 1], c0, c1);
        }
        float cs[4];
#pragma unroll
        for (int c = 0; c < 4; c++) cs[c] = csA[c] + csB[c];

        // ---- online softmax ----
        float cm0 = fmaxf(cs[0], cs[1]);
        cm0 = fmaxf(cm0, __shfl_xor_sync(0xffffffffu, cm0, 1));
        cm0 = fmaxf(cm0, __shfl_xor_sync(0xffffffffu, cm0, 2));
        float cm1 = fmaxf(cs[2], cs[3]);
        cm1 = fmaxf(cm1, __shfl_xor_sync(0xffffffffu, cm1, 1));
        cm1 = fmaxf(cm1, __shfl_xor_sync(0xffffffffu, cm1, 2));
        float nm0 = fmaxf(m0, cm0), nm1 = fmaxf(m1, cm1);
        float f0 = __expf(m0 - nm0), f1 = __expf(m1 - nm1);
        float p0 = __expf(cs[0] - nm0), p1 = __expf(cs[1] - nm0);
        float p2 = __expf(cs[2] - nm1), p3 = __expf(cs[3] - nm1);
        float rs0 = p0 + p1, rs1 = p2 + p3;
        rs0 += __shfl_xor_sync(0xffffffffu, rs0, 1);
        rs0 += __shfl_xor_sync(0xffffffffu, rs0, 2);
        rs1 += __shfl_xor_sync(0xffffffffu, rs1, 1);
        rs1 += __shfl_xor_sync(0xffffffffu, rs1, 2);
        l0 = l0 * f0 + rs0;
        l1 = l1 * f1 + rs1;
        m0 = nm0; m1 = nm1;
        if (__any_sync(0xffffffffu, (f0 < 1.f) || (f1 < 1.f))) {
#pragma unroll
            for (int j = 0; j < 16; j++) {
                acc[j][0] *= f0; acc[j][1] *= f0;
                acc[j][2] *= f1; acc[j][3] *= f1;
            }
        }
        // ---- rearrange P -> A-fragment layout ----
        int srcA = (lane & 28) | (tg >> 1);
        int srcB = srcA | 2;
        float x0 = __shfl_sync(0xffffffffu, p0, srcA), x1 = __shfl_sync(0xffffffffu, p1, srcA);
        float y0 = __shfl_sync(0xffffffffu, p0, srcB), y1 = __shfl_sync(0xffffffffu, p1, srcB);
        float z0 = __shfl_sync(0xffffffffu, p2, srcA), z1 = __shfl_sync(0xffffffffu, p3, srcA);
        float w0 = __shfl_sync(0xffffffffu, p2, srcB), w1 = __shfl_sync(0xffffffffu, p3, srcB);
        bool odd = (tg & 1) != 0;
        unsigned pa[4];
        pa[0] = f2tf32(odd ? x1 : x0);
        pa[1] = f2tf32(odd ? z1 : z0);
        pa[2] = f2tf32(odd ? y1 : y0);
        pa[3] = f2tf32(odd ? w1 : w0);

        // wait for V_t
        if (tile + 1 < NT) asm volatile("cp.async.wait_group 2;" ::: "memory");
        else               asm volatile("cp.async.wait_group 0;" ::: "memory");
        __syncthreads();

        const float* VT = Vs + buf * SMV_STAGE + wid * 8 * VROWV;
#pragma unroll
        for (int j = 0; j < 16; j++) {
            unsigned b0 = f2tf32(VT[tg * VROWV + j * 8 + gl]);
            unsigned b1 = f2tf32(VT[(tg + 4) * VROWV + j * 8 + gl]);
            mma8(acc[j], pa, b0, b1);
        }
    }

    // ---- in-block combine of the 4 warp partials (reuse smem) ----
    __syncthreads();
    float* sacc = sm;                    // [4][16][132]
    float* smm  = sm + 4 * 16 * 132;     // [4][16]
    float* sml  = smm + 64;              // [4][16]
    float* mine = sacc + wid * 16 * 132;
#pragma unroll
    for (int j = 0; j < 16; j++) {
        mine[gl * 132 + j * 8 + 2 * tg]           = acc[j][0];
        mine[gl * 132 + j * 8 + 2 * tg + 1]       = acc[j][1];
        mine[(gl + 8) * 132 + j * 8 + 2 * tg]     = acc[j][2];
        mine[(gl + 8) * 132 + j * 8 + 2 * tg + 1] = acc[j][3];
    }
    if (tg == 0) {
        smm[wid * 16 + gl]     = m0;
        smm[wid * 16 + gl + 8] = m1;
        sml[wid * 16 + gl]     = l0;
        sml[wid * 16 + gl + 8] = l1;
    }
    __syncthreads();

    const int p = bg * NSPLIT + sub;
    float* po = g_part_acc + (size_t)p * 2048;
#pragma unroll
    for (int row = 0; row < 16; row++) {
        float ma = fmaxf(fmaxf(smm[row], smm[16 + row]), fmaxf(smm[32 + row], smm[48 + row]));
        float e0 = __expf(smm[row] - ma);
        float e1 = __expf(smm[16 + row] - ma);
        float e2 = __expf(smm[32 + row] - ma);
        float e3 = __expf(smm[48 + row] - ma);
        float s = sacc[row * 132 + tid] * e0
                + sacc[(16 + row) * 132 + tid] * e1
                + sacc[(32 + row) * 132 + tid] * e2
                + sacc[(48 + row) * 132 + tid] * e3;
        po[row * 128 + tid] = s;
        if (tid == 0) {
            g_part_m[p * 16 + row] = ma;
            g_part_l[p * 16 + row] = sml[row] * e0 + sml[16 + row] * e1
                                   + sml[32 + row] * e2 + sml[48 + row] * e3;
        }
    }
}

// ---------------- combine: one thread per output element, 8 partials ----------------
__global__ void __launch_bounds__(256) combine_kernel()
{
    int idx = blockIdx.x * 256 + threadIdx.x;   // 0..262143
    int bg  = idx >> 11;
    int row = (idx >> 7) & 15;
    int d   = idx & 127;
    float M = -1e30f;
#pragma unroll
    for (int sp = 0; sp < NSPLIT; sp++)
        M = fmaxf(M, g_part_m[(bg * NSPLIT + sp) * 16 + row]);
    float sum = 0.f, L = 0.f;
#pragma unroll
    for (int sp = 0; sp < NSPLIT; sp++) {
        int pp = bg * NSPLIT + sp;
        float w = __expf(g_part_m[pp * 16 + row] - M);
        L   += g_part_l[pp * 16 + row] * w;
        sum += g_part_acc[(size_t)pp * 2048 + row * 128 + d] * w;
    }
    float o = sum / L;
    int b = bg >> 3, g = bg & 7;
    int h = g * 4 + (row >> 2);
    int s = row & 3;
    int m = b * 4 + s;
    g_ao[(size_t)m * 4096 + h * 128 + d] = o;
}

// ---------------- launch ----------------
extern "C" void kernel_launch(void* const* d_in, const int* in_sizes, int n_in,
                              void* d_out, int out_size)
{
    const float* hs = (const float*)d_in[0];
    const float* kc = (const float*)d_in[2];
    const float* vc = (const float*)d_in[3];
    const float* qw = (const float*)d_in[5];
    const float* qb = (const float*)d_in[6];
    const float* kw = (const float*)d_in[7];
    const float* kb = (const float*)d_in[8];
    const float* vw = (const float*)d_in[9];
    const float* vb = (const float*)d_in[10];
    const float* ow = (const float*)d_in[11];

    float* out  = (float*)d_out;
    float* knew = out + KNEW_OFF;
    float* vnew = out + VNEW_OFF;

    cudaFuncSetAttribute(attn2, cudaFuncAttributeMaxDynamicSharedMemorySize, (int)SMEM_ATTN);
    cudaFuncSetAttribute(qkv_gemm, cudaFuncAttributeMaxDynamicSharedMemorySize, (int)GEMM_SMEM);
    cudaFuncSetAttribute(o_gemm, cudaFuncAttributeMaxDynamicSharedMemorySize, (int)GEMM_SMEM);

    qkv_gemm<<<96, 128, GEMM_SMEM>>>(hs, qw, qb, kw, kb, vw, vb);
    rope_scatter<<<896, 256>>>(knew, vnew);
    attn2<<<1024, 128, SMEM_ATTN>>>(kc, vc, knew, vnew);
    combine_kernel<<<1024, 256>>>();
    o_gemm<<<64, 128, GEMM_SMEM>>>(ow, out);
}

// round 9
// speedup vs baseline: 1.5551x; 1.5551x over previous
#include <cuda_runtime.h>
#include <cuda_bf16.h>
#include <cstdint>

// Problem constants
#define BB    16
#define SS    4
#define HID   4096
#define HH    32
#define KVH   8
#define DD    128
#define T0    4092      // START_POS
#define TT    4096
#define M64   64        // B*S rows
#define SCALE 0.08838834764831845f  // 1/sqrt(128)

#define OUT_ELEMS  (M64*HID)
#define KNEW_OFF   OUT_ELEMS
#define VNEW_OFF   (OUT_ELEMS + BB*KVH*SS*DD)

#define NSPLIT 8                 // key splits per (b,kv)
#define NPART  (BB*KVH*NSPLIT)   // 1024 block partials

#define KSL 4                    // GEMM split-K factor
#define NQKV 6144                // fused qkv N space: [0,4096)=q [4096,5120)=k [5120,6144)=v
#define QKVP_SL (M64*NQKV)       // per-slice partial size
#define OP_SL   (M64*HID)

// ---------------- scratch ----------------
__device__ float g_qkvp[KSL*QKVP_SL];     // qkv projection partials [ksl][m][NQKV]
__device__ float g_op[KSL*OP_SL];         // o-proj partials [ksl][m][4096]
__device__ float g_q[BB*KVH*16*DD];       // [bg][row16][d], rope'd, *SCALE
__device__ float g_part_acc[NPART*16*DD];
__device__ float g_part_m[NPART*16];
__device__ float g_part_l[NPART*16];
__device__ float g_ao[M64*HID];

// ---------------- helpers ----------------
__device__ __forceinline__ unsigned f2tf32(float x) {
    unsigned r;
    asm("cvt.rna.tf32.f32 %0, %1;" : "=r"(r) : "f"(x));
    return r;
}
__device__ __forceinline__ void mma8(float d[4], const unsigned a[4], unsigned b0, unsigned b1) {
    asm volatile(
        "mma.sync.aligned.m16n8k8.row.col.f32.tf32.tf32.f32 "
        "{%0,%1,%2,%3}, {%4,%5,%6,%7}, {%8,%9}, {%0,%1,%2,%3};"
        : "+f"(d[0]), "+f"(d[1]), "+f"(d[2]), "+f"(d[3])
        : "r"(a[0]), "r"(a[1]), "r"(a[2]), "r"(a[3]), "r"(b0), "r"(b1));
}
__device__ __forceinline__ void cpa16(void* dst, const void* src) {
    unsigned d = (unsigned)__cvta_generic_to_shared(dst);
    asm volatile("cp.async.cg.shared.global [%0], [%1], 16;" :: "r"(d), "l"(src));
}
#define CPA_COMMIT() asm volatile("cp.async.commit_group;" ::: "memory")

// ================= GEMM: 64(M)x64(N) tile, BK=32, split-K, 4-stage cp.async =========
#define GST 4
#define GSTRIDE 36
#define GSTAGE_F (64*GSTRIDE)
#define GEMM_SMEM (GST*GSTAGE_F*2*sizeof(float))   // 73728 B
#define KITERS 32                                  // 1024 K per slice

__device__ __forceinline__ void gemm_body(
    const float* __restrict__ A, const float* __restrict__ W,
    const float* __restrict__ bias, float* __restrict__ C, int ldc, int n0,
    int kbase, float* sm)
{
    float* As = sm;
    float* Ws = sm + GST * GSTAGE_F;
    const int t = threadIdx.x;
    const int wid = t >> 5, lane = t & 31;
    const int gl = lane >> 2, tg = lane & 3;
    const int mb = (wid >> 1) * 32, nb = (wid & 1) * 32;

    float acc[2][4][4];
#pragma unroll
    for (int a = 0; a < 2; a++)
#pragma unroll
        for (int b = 0; b < 4; b++)
#pragma unroll
            for (int c = 0; c < 4; c++) acc[a][b][c] = 0.f;

    auto stage = [&](int s, int k0) {
#pragma unroll
        for (int i = 0; i < 4; i++) {
            int f = t + i * 128;
            int row = f >> 3, c4 = (f & 7) * 4;
            cpa16(&As[s * GSTAGE_F + row * GSTRIDE + c4], A + (size_t)row * 4096 + k0 + c4);
            cpa16(&Ws[s * GSTAGE_F + row * GSTRIDE + c4], W + (size_t)(n0 + row) * 4096 + k0 + c4);
        }
        CPA_COMMIT();
    };

    stage(0, kbase); stage(1, kbase + 32); stage(2, kbase + 64);

    for (int it = 0; it < KITERS; it++) {
        if (it < KITERS - 2)       asm volatile("cp.async.wait_group 2;" ::: "memory");
        else if (it == KITERS - 2) asm volatile("cp.async.wait_group 1;" ::: "memory");
        else                       asm volatile("cp.async.wait_group 0;" ::: "memory");
        __syncthreads();
        if (it + 3 < KITERS) stage((it + 3) & 3, kbase + (it + 3) * 32);

        const float* as = As + (it & 3) * GSTAGE_F;
        const float* ws = Ws + (it & 3) * GSTAGE_F;
#pragma unroll
        for (int kk = 0; kk < 4; kk++) {
            unsigned a[2][4];
#pragma unroll
            for (int tt2 = 0; tt2 < 2; tt2++) {
                int r0 = mb + tt2 * 16 + gl;
                a[tt2][0] = f2tf32(as[r0 * GSTRIDE + kk * 8 + tg]);
                a[tt2][1] = f2tf32(as[(r0 + 8) * GSTRIDE + kk * 8 + tg]);
                a[tt2][2] = f2tf32(as[r0 * GSTRIDE + kk * 8 + tg + 4]);
                a[tt2][3] = f2tf32(as[(r0 + 8) * GSTRIDE + kk * 8 + tg + 4]);
            }
#pragma unroll
            for (int j = 0; j < 4; j++) {
                unsigned b0 = f2tf32(ws[(nb + j * 8 + gl) * GSTRIDE + kk * 8 + tg]);
                unsigned b1 = f2tf32(ws[(nb + j * 8 + gl) * GSTRIDE + kk * 8 + tg + 4]);
                mma8(acc[0][j], a[0], b0, b1);
                mma8(acc[1][j], a[1], b0, b1);
            }
        }
    }
#pragma unroll
    for (int tt2 = 0; tt2 < 2; tt2++)
#pragma unroll
        for (int j = 0; j < 4; j++) {
            int r0 = mb + tt2 * 16 + gl;
            int col = n0 + nb + j * 8 + 2 * tg;
            float b0v = 0.f, b1v = 0.f;
            if (bias) { b0v = bias[col]; b1v = bias[col + 1]; }
            C[(size_t)r0 * ldc + col]           = acc[tt2][j][0] + b0v;
            C[(size_t)r0 * ldc + col + 1]       = acc[tt2][j][1] + b1v;
            C[(size_t)(r0 + 8) * ldc + col]     = acc[tt2][j][2] + b0v;
            C[(size_t)(r0 + 8) * ldc + col + 1] = acc[tt2][j][3] + b1v;
        }
}

// Fused QKV with split-K: 96 N-tiles x 4 k-slices = 384 blocks
__global__ void __launch_bounds__(128, 2) qkv_gemm(
    const float* __restrict__ A,
    const float* __restrict__ qw, const float* __restrict__ qb,
    const float* __restrict__ kw, const float* __restrict__ kb,
    const float* __restrict__ vw, const float* __restrict__ vb)
{
    extern __shared__ float gsm[];
    int nt  = blockIdx.x % 96;
    int ksl = blockIdx.x / 96;
    int kbase = ksl * 1024;
    float* Cp = g_qkvp + (size_t)ksl * QKVP_SL;
    if (nt < 64)
        gemm_body(A, qw, (ksl == 0) ? qb : nullptr, Cp, NQKV, nt * 64, kbase, gsm);
    else if (nt < 80)
        gemm_body(A, kw, (ksl == 0) ? kb : nullptr, Cp + 4096, NQKV, (nt - 64) * 64, kbase, gsm);
    else
        gemm_body(A, vw, (ksl == 0) ? vb : nullptr, Cp + 5120, NQKV, (nt - 80) * 64, kbase, gsm);
}

// O projection with split-K: 64 N-tiles x 4 k-slices = 256 blocks
__global__ void __launch_bounds__(128, 2) o_gemm(const float* __restrict__ ow)
{
    extern __shared__ float gsm[];
    int nt  = blockIdx.x % 64;
    int ksl = blockIdx.x / 64;
    gemm_body(g_ao, ow, nullptr, g_op + (size_t)ksl * OP_SL, HID, nt * 64, ksl * 1024, gsm);
}

// reduce 4 o-partials -> out
__global__ void __launch_bounds__(256) o_reduce(float* __restrict__ out)
{
    int idx = blockIdx.x * 256 + threadIdx.x;   // 0..262143
    out[idx] = g_op[idx] + g_op[OP_SL + idx] + g_op[2 * OP_SL + idx] + g_op[3 * OP_SL + idx];
}

// ---------------- RoPE + scatter (positions[b][s] == b*S+s); sums 4 qkv partials ----
__device__ __forceinline__ float qkvp_sum(int m, int col) {
    return g_qkvp[(size_t)m * NQKV + col]
         + g_qkvp[QKVP_SL + (size_t)m * NQKV + col]
         + g_qkvp[2 * QKVP_SL + (size_t)m * NQKV + col]
         + g_qkvp[3 * QKVP_SL + (size_t)m * NQKV + col];
}

__global__ void __launch_bounds__(256) rope_scatter(
    float* __restrict__ knew, float* __restrict__ vnew)
{
    int idx = blockIdx.x * 256 + threadIdx.x;
    const float NEG_LOG2_BASE_OVER_HALF = -13.287712379549449f / 64.f;
    if (idx < 131072) {                       // Q
        int d0 = idx & 63;
        int h  = (idx >> 6) & 31;
        int m  = idx >> 11;
        int b = m >> 2, s = m & 3;
        float ang = (float)m * exp2f((float)d0 * NEG_LOG2_BASE_OVER_HALF);
        float c = cosf(ang), sn = sinf(ang);
        float x1 = qkvp_sum(m, h * 128 + d0);
        float x2 = qkvp_sum(m, h * 128 + d0 + 64);
        int g = h >> 2, r = h & 3, row = r * 4 + s;
        int base = ((b * 8 + g) * 16 + row) * 128;
        g_q[base + d0]      = (x1 * c - x2 * sn) * SCALE;
        g_q[base + d0 + 64] = (x2 * c + x1 * sn) * SCALE;
    } else if (idx < 163840) {                // K
        int j = idx - 131072;
        int d0 = j & 63;
        int kv = (j >> 6) & 7;
        int m  = j >> 9;
        int b = m >> 2, s = m & 3;
        float ang = (float)m * exp2f((float)d0 * NEG_LOG2_BASE_OVER_HALF);
        float c = cosf(ang), sn = sinf(ang);
        float x1 = qkvp_sum(m, 4096 + kv * 128 + d0);
        float x2 = qkvp_sum(m, 4096 + kv * 128 + d0 + 64);
        int base = ((b * 8 + kv) * 4 + s) * 128;
        knew[base + d0]      = x1 * c - x2 * sn;
        knew[base + d0 + 64] = x2 * c + x1 * sn;
    } else if (idx < 229376) {                // V
        int j = idx - 163840;
        int d  = j & 127;
        int kv = (j >> 7) & 7;
        int m  = j >> 10;
        int b = m >> 2, s = m & 3;
        vnew[((b * 8 + kv) * 4 + s) * 128 + d] = qkvp_sum(m, 5120 + kv * 128 + d);
    }
}

// ================= Attention =================
// grid 1024: bg = blk>>3, sub = blk&7 -> keys [sub*512, +512), 16 tiles of 32.
// 4 warps; Q fragments staged in smem (keeps regs under 128, no spills).
#define NT 16
#define KROWK 132
#define VROWV 136
#define SMK_STAGE (32*KROWK)
#define SMV_STAGE (32*VROWV)
#define QS_OFF (2*SMK_STAGE + 2*SMV_STAGE)
#define SMEM_ATTN ((QS_OFF + 16*132) * sizeof(float))   // 77056 B

__global__ void __launch_bounds__(128, 2) attn2(
    const float* __restrict__ kc, const float* __restrict__ vc,
    const float* __restrict__ knew, const float* __restrict__ vnew)
{
    extern __shared__ float sm[];
    float* Ks = sm;                        // [2][32][132]
    float* Vs = sm + 2 * SMK_STAGE;        // [2][32][136]
    float* Qs = sm + QS_OFF;               // [16][132]

    const int tid = threadIdx.x, wid = tid >> 5, lane = tid & 31;
    const int gl = lane >> 2, tg = lane & 3;
    const int bg = blockIdx.x >> 3, sub = blockIdx.x & 7;
    const int kbase = sub * 512;

    const float* kcb = kc + (size_t)bg * TT * DD;
    const float* vcb = vc + (size_t)bg * TT * DD;
    const float* knb = knew + (size_t)bg * SS * DD;
    const float* vnb = vnew + (size_t)bg * SS * DD;

    // stage Q (16x128) into smem once
    {
        const float* q = g_q + (size_t)bg * 2048;
#pragma unroll
        for (int i = 0; i < 4; i++) {
            int f = tid + i * 128;               // float4 idx 0..511
            int row = f >> 5, c4 = (f & 31) * 4;
            *reinterpret_cast<float4*>(&Qs[row * 132 + c4]) =
                *reinterpret_cast<const float4*>(q + row * 128 + c4);
        }
    }

    float acc[16][4];
#pragma unroll
    for (int j = 0; j < 16; j++)
#pragma unroll
        for (int c = 0; c < 4; c++) acc[j][c] = 0.f;
    float m0 = -1e30f, m1 = -1e30f, l0 = 0.f, l1 = 0.f;

    auto stageK = [&](int buf, int tile) {
        int key0 = kbase + tile * 32;
        float* kd = Ks + buf * SMK_STAGE;
        if (key0 + 32 <= T0) {
            const char* ksrc = (const char*)(kcb + (size_t)key0 * DD);
#pragma unroll
            for (int i = 0; i < 8; i++) {
                int f = tid + i * 128;
                int row = f >> 5, c4 = (f & 31) * 4;
                cpa16(&kd[row * KROWK + c4], ksrc + (size_t)f * 16);
            }
        } else {
#pragma unroll
            for (int i = 0; i < 8; i++) {
                int f = tid + i * 128;
                int row = f >> 5, c4 = (f & 31) * 4;
                int t = key0 + row;
                const float* ks = (t < T0) ? (kcb + (size_t)t * DD + c4) : (knb + (size_t)(t - T0) * DD + c4);
                cpa16(&kd[row * KROWK + c4], ks);
            }
        }
        CPA_COMMIT();
    };
    auto stageV = [&](int buf, int tile) {
        int key0 = kbase + tile * 32;
        float* vd = Vs + buf * SMV_STAGE;
        if (key0 + 32 <= T0) {
            const char* vsrc = (const char*)(vcb + (size_t)key0 * DD);
#pragma unroll
            for (int i = 0; i < 8; i++) {
                int f = tid + i * 128;
                int row = f >> 5, c4 = (f & 31) * 4;
                cpa16(&vd[row * VROWV + c4], vsrc + (size_t)f * 16);
            }
        } else {
#pragma unroll
            for (int i = 0; i < 8; i++) {
                int f = tid + i * 128;
                int row = f >> 5, c4 = (f & 31) * 4;
                int t = key0 + row;
                const float* vs = (t < T0) ? (vcb + (size_t)t * DD + c4) : (vnb + (size_t)(t - T0) * DD + c4);
                cpa16(&vd[row * VROWV + c4], vs);
            }
        }
        CPA_COMMIT();
    };

    stageK(0, 0);
    stageV(0, 0);

#pragma unroll 1
    for (int tile = 0; tile < NT; tile++) {
        int buf = tile & 1;
        asm volatile("cp.async.wait_group 1;" ::: "memory");   // K_t done (V_t may be in flight)
        __syncthreads();
        if (tile + 1 < NT) {
            stageK(buf ^ 1, tile + 1);
            stageV(buf ^ 1, tile + 1);
        }

        // ---- QK^T: 2 independent mma chains, Q frags from smem ----
        const float* KT = Ks + buf * SMK_STAGE + wid * 8 * KROWK;
        float csA[4] = {0.f, 0.f, 0.f, 0.f};
        float csB[4] = {0.f, 0.f, 0.f, 0.f};
#pragma unroll
        for (int kk = 0; kk < 16; kk += 2) {
            unsigned aA[4], aB[4];
            aA[0] = f2tf32(Qs[gl * 132 + kk * 8 + tg]);
            aA[1] = f2tf32(Qs[(gl + 8) * 132 + kk * 8 + tg]);
            aA[2] = f2tf32(Qs[gl * 132 + kk * 8 + tg + 4]);
            aA[3] = f2tf32(Qs[(gl + 8) * 132 + kk * 8 + tg + 4]);
            unsigned b0 = f2tf32(KT[gl * KROWK + kk * 8 + tg]);
            unsigned b1 = f2tf32(KT[gl * KROWK + kk * 8 + tg + 4]);
            mma8(csA, aA, b0, b1);
            aB[0] = f2tf32(Qs[gl * 132 + kk * 8 + 8 + tg]);
            aB[1] = f2tf32(Qs[(gl + 8) * 132 + kk * 8 + 8 + tg]);
            aB[2] = f2tf32(Qs[gl * 132 + kk * 8 + 8 + tg + 4]);
            aB[3] = f2tf32(Qs[(gl + 8) * 132 + kk * 8 + 8 + tg + 4]);
            unsigned c0 = f2tf32(KT[gl * KROWK + kk * 8 + 8 + tg]);
            unsigned c1 = f2tf32(KT[gl * KROWK + kk * 8 + 8 + tg + 4]);
            mma8(csB, aB, c0, c1);
        }
        float cs[4];
#pragma unroll
        for (int c = 0; c < 4; c++) cs[c] = csA[c] + csB[c];

        // ---- online softmax ----
        float cm0 = fmaxf(cs[0], cs[1]);
        cm0 = fmaxf(cm0, __shfl_xor_sync(0xffffffffu, cm0, 1));
        cm0 = fmaxf(cm0, __shfl_xor_sync(0xffffffffu, cm0, 2));
        float cm1 = fmaxf(cs[2], cs[3]);
        cm1 = fmaxf(cm1, __shfl_xor_sync(0xffffffffu, cm1, 1));
        cm1 = fmaxf(cm1, __shfl_xor_sync(0xffffffffu, cm1, 2));
        float nm0 = fmaxf(m0, cm0), nm1 = fmaxf(m1, cm1);
        float f0 = __expf(m0 - nm0), f1 = __expf(m1 - nm1);
        float p0 = __expf(cs[0] - nm0), p1 = __expf(cs[1] - nm0);
        float p2 = __expf(cs[2] - nm1), p3 = __expf(cs[3] - nm1);
        float rs0 = p0 + p1, rs1 = p2 + p3;
        rs0 += __shfl_xor_sync(0xffffffffu, rs0, 1);
        rs0 += __shfl_xor_sync(0xffffffffu, rs0, 2);
        rs1 += __shfl_xor_sync(0xffffffffu, rs1, 1);
        rs1 += __shfl_xor_sync(0xffffffffu, rs1, 2);
        l0 = l0 * f0 + rs0;
        l1 = l1 * f1 + rs1;
        m0 = nm0; m1 = nm1;
        if (__any_sync(0xffffffffu, (f0 < 1.f) || (f1 < 1.f))) {
#pragma unroll
            for (int j = 0; j < 16; j++) {
                acc[j][0] *= f0; acc[j][1] *= f0;
                acc[j][2] *= f1; acc[j][3] *= f1;
            }
        }
        // ---- rearrange P -> A-fragment layout ----
        int srcA = (lane & 28) | (tg >> 1);
        int srcB = srcA | 2;
        float x0 = __shfl_sync(0xffffffffu, p0, srcA), x1 = __shfl_sync(0xffffffffu, p1, srcA);
        float y0 = __shfl_sync(0xffffffffu, p0, srcB), y1 = __shfl_sync(0xffffffffu, p1, srcB);
        float z0 = __shfl_sync(0xffffffffu, p2, srcA), z1 = __shfl_sync(0xffffffffu, p3, srcA);
        float w0 = __shfl_sync(0xffffffffu, p2, srcB), w1 = __shfl_sync(0xffffffffu, p3, srcB);
        bool odd = (tg & 1) != 0;
        unsigned pa[4];
        pa[0] = f2tf32(odd ? x1 : x0);
        pa[1] = f2tf32(odd ? z1 : z0);
        pa[2] = f2tf32(odd ? y1 : y0);
        pa[3] = f2tf32(odd ? w1 : w0);

        if (tile + 1 < NT) asm volatile("cp.async.wait_group 2;" ::: "memory");
        else               asm volatile("cp.async.wait_group 0;" ::: "memory");
        __syncthreads();

        const float* VT = Vs + buf * SMV_STAGE + wid * 8 * VROWV;
#pragma unroll
        for (int j = 0; j < 16; j++) {
            unsigned b0 = f2tf32(VT[tg * VROWV + j * 8 + gl]);
            unsigned b1 = f2tf32(VT[(tg + 4) * VROWV + j * 8 + gl]);
            mma8(acc[j], pa, b0, b1);
        }
    }

    // ---- in-block combine of the 4 warp partials (reuse smem) ----
    __syncthreads();
    float* sacc = sm;                    // [4][16][132]
    float* smm  = sm + 4 * 16 * 132;     // [4][16]
    float* sml  = smm + 64;              // [4][16]
    float* mine = sacc + wid * 16 * 132;
#pragma unroll
    for (int j = 0; j < 16; j++) {
        mine[gl * 132 + j * 8 + 2 * tg]           = acc[j][0];
        mine[gl * 132 + j * 8 + 2 * tg + 1]       = acc[j][1];
        mine[(gl + 8) * 132 + j * 8 + 2 * tg]     = acc[j][2];
        mine[(gl + 8) * 132 + j * 8 + 2 * tg + 1] = acc[j][3];
    }
    if (tg == 0) {
        smm[wid * 16 + gl]     = m0;
        smm[wid * 16 + gl + 8] = m1;
        sml[wid * 16 + gl]     = l0;
        sml[wid * 16 + gl + 8] = l1;
    }
    __syncthreads();

    const int p = bg * NSPLIT + sub;
    float* po = g_part_acc + (size_t)p * 2048;
#pragma unroll
    for (int row = 0; row < 16; row++) {
        float ma = fmaxf(fmaxf(smm[row], smm[16 + row]), fmaxf(smm[32 + row], smm[48 + row]));
        float e0 = __expf(smm[row] - ma);
        float e1 = __expf(smm[16 + row] - ma);
        float e2 = __expf(smm[32 + row] - ma);
        float e3 = __expf(smm[48 + row] - ma);
        float s = sacc[row * 132 + tid] * e0
                + sacc[(16 + row) * 132 + tid] * e1
                + sacc[(32 + row) * 132 + tid] * e2
                + sacc[(48 + row) * 132 + tid] * e3;
        po[row * 128 + tid] = s;
        if (tid == 0) {
            g_part_m[p * 16 + row] = ma;
            g_part_l[p * 16 + row] = sml[row] * e0 + sml[16 + row] * e1
                                   + sml[32 + row] * e2 + sml[48 + row] * e3;
        }
    }
}

// ---------------- combine: one thread per output element, 8 partials ----------------
__global__ void __launch_bounds__(256) combine_kernel()
{
    int idx = blockIdx.x * 256 + threadIdx.x;   // 0..262143
    int bg  = idx >> 11;
    int row = (idx >> 7) & 15;
    int d   = idx & 127;
    float M = -1e30f;
#pragma unroll
    for (int sp = 0; sp < NSPLIT; sp++)
        M = fmaxf(M, g_part_m[(bg * NSPLIT + sp) * 16 + row]);
    float sum = 0.f, L = 0.f;
#pragma unroll
    for (int sp = 0; sp < NSPLIT; sp++) {
        int pp = bg * NSPLIT + sp;
        float w = __expf(g_part_m[pp * 16 + row] - M);
        L   += g_part_l[pp * 16 + row] * w;
        sum += g_part_acc[(size_t)pp * 2048 + row * 128 + d] * w;
    }
    float o = sum / L;
    int b = bg >> 3, g = bg & 7;
    int h = g * 4 + (row >> 2);
    int s = row & 3;
    int m = b * 4 + s;
    g_ao[(size_t)m * 4096 + h * 128 + d] = o;
}

// ---------------- launch ----------------
extern "C" void kernel_launch(void* const* d_in, const int* in_sizes, int n_in,
                              void* d_out, int out_size)
{
    const float* hs = (const float*)d_in[0];
    const float* kc = (const float*)d_in[2];
    const float* vc = (const float*)d_in[3];
    const float* qw = (const float*)d_in[5];
    const float* qb = (const float*)d_in[6];
    const float* kw = (const float*)d_in[7];
    const float* kb = (const float*)d_in[8];
    const float* vw = (const float*)d_in[9];
    const float* vb = (const float*)d_in[10];
    const float* ow = (const float*)d_in[11];

    float* out  = (float*)d_out;
    float* knew = out + KNEW_OFF;
    float* vnew = out + VNEW_OFF;

    cudaFuncSetAttribute(attn2, cudaFuncAttributeMaxDynamicSharedMemorySize, (int)SMEM_ATTN);
    cudaFuncSetAttribute(qkv_gemm, cudaFuncAttributeMaxDynamicSharedMemorySize, (int)GEMM_SMEM);
    cudaFuncSetAttribute(o_gemm, cudaFuncAttributeMaxDynamicSharedMemorySize, (int)GEMM_SMEM);

    qkv_gemm<<<384, 128, GEMM_SMEM>>>(hs, qw, qb, kw, kb, vw, vb);
    rope_scatter<<<896, 256>>>(knew, vnew);
    attn2<<<1024, 128, SMEM_ATTN>>>(kc, vc, knew, vnew);
    combine_kernel<<<1024, 256>>>();
    o_gemm<<<256, 128, GEMM_SMEM>>>(ow);
    o_reduce<<<1024, 256>>>(out);
}

// round 10
// speedup vs baseline: 1.6125x; 1.0369x over previous
#include <cuda_runtime.h>
#include <cuda_bf16.h>
#include <cstdint>

// Problem constants
#define BB    16
#define SS    4
#define HID   4096
#define HH    32
#define KVH   8
#define DD    128
#define T0    4092      // START_POS
#define TT    4096
#define M64   64        // B*S rows
#define SCALE 0.08838834764831845f  // 1/sqrt(128)

#define OUT_ELEMS  (M64*HID)
#define KNEW_OFF   OUT_ELEMS
#define VNEW_OFF   (OUT_ELEMS + BB*KVH*SS*DD)

#define NSPLIT 8                 // key splits per (b,kv)
#define NPART  (BB*KVH*NSPLIT)   // 1024 block partials

#define KSL 4                    // GEMM split-K factor
#define NQKV 6144                // fused qkv N space: [0,4096)=q [4096,5120)=k [5120,6144)=v
#define QKVP_SL (M64*NQKV)
#define OP_SL   (M64*HID)

// ---------------- scratch ----------------
__device__ float g_qkvp[KSL*QKVP_SL];
__device__ float g_op[KSL*OP_SL];
__device__ float g_q[BB*KVH*16*DD];       // [bg][row16][d], rope'd, *SCALE
__device__ float g_part_acc[NPART*16*DD];
__device__ float g_part_m[NPART*16];
__device__ float g_part_l[NPART*16];
__device__ float g_ao[M64*HID];

// ---------------- helpers ----------------
__device__ __forceinline__ unsigned f2tf32(float x) {
    unsigned r;
    asm("cvt.rna.tf32.f32 %0, %1;" : "=r"(r) : "f"(x));
    return r;
}
__device__ __forceinline__ void mma8(float d[4], const unsigned a[4], unsigned b0, unsigned b1) {
    asm volatile(
        "mma.sync.aligned.m16n8k8.row.col.f32.tf32.tf32.f32 "
        "{%0,%1,%2,%3}, {%4,%5,%6,%7}, {%8,%9}, {%0,%1,%2,%3};"
        : "+f"(d[0]), "+f"(d[1]), "+f"(d[2]), "+f"(d[3])
        : "r"(a[0]), "r"(a[1]), "r"(a[2]), "r"(a[3]), "r"(b0), "r"(b1));
}
__device__ __forceinline__ void cpa16(void* dst, const void* src) {
    unsigned d = (unsigned)__cvta_generic_to_shared(dst);
    asm volatile("cp.async.cg.shared.global [%0], [%1], 16;" :: "r"(d), "l"(src));
}
#define CPA_COMMIT() asm volatile("cp.async.commit_group;" ::: "memory")

// ================= GEMM: 64(M)x64(N) tile, BK=32, split-K, 4-stage cp.async =========
#define GST 4
#define GSTRIDE 36
#define GSTAGE_F (64*GSTRIDE)
#define GEMM_SMEM (GST*GSTAGE_F*2*sizeof(float))   // 73728 B
#define KITERS 32

__device__ __forceinline__ void gemm_body(
    const float* __restrict__ A, const float* __restrict__ W,
    const float* __restrict__ bias, float* __restrict__ C, int ldc, int n0,
    int kbase, float* sm)
{
    float* As = sm;
    float* Ws = sm + GST * GSTAGE_F;
    const int t = threadIdx.x;
    const int wid = t >> 5, lane = t & 31;
    const int gl = lane >> 2, tg = lane & 3;
    const int mb = (wid >> 1) * 32, nb = (wid & 1) * 32;

    float acc[2][4][4];
#pragma unroll
    for (int a = 0; a < 2; a++)
#pragma unroll
        for (int b = 0; b < 4; b++)
#pragma unroll
            for (int c = 0; c < 4; c++) acc[a][b][c] = 0.f;

    auto stage = [&](int s, int k0) {
#pragma unroll
        for (int i = 0; i < 4; i++) {
            int f = t + i * 128;
            int row = f >> 3, c4 = (f & 7) * 4;
            cpa16(&As[s * GSTAGE_F + row * GSTRIDE + c4], A + (size_t)row * 4096 + k0 + c4);
            cpa16(&Ws[s * GSTAGE_F + row * GSTRIDE + c4], W + (size_t)(n0 + row) * 4096 + k0 + c4);
        }
        CPA_COMMIT();
    };

    stage(0, kbase); stage(1, kbase + 32); stage(2, kbase + 64);

    for (int it = 0; it < KITERS; it++) {
        if (it < KITERS - 2)       asm volatile("cp.async.wait_group 2;" ::: "memory");
        else if (it == KITERS - 2) asm volatile("cp.async.wait_group 1;" ::: "memory");
        else                       asm volatile("cp.async.wait_group 0;" ::: "memory");
        __syncthreads();
        if (it + 3 < KITERS) stage((it + 3) & 3, kbase + (it + 3) * 32);

        const float* as = As + (it & 3) * GSTAGE_F;
        const float* ws = Ws + (it & 3) * GSTAGE_F;
#pragma unroll
        for (int kk = 0; kk < 4; kk++) {
            unsigned a[2][4];
#pragma unroll
            for (int tt2 = 0; tt2 < 2; tt2++) {
                int r0 = mb + tt2 * 16 + gl;
                a[tt2][0] = f2tf32(as[r0 * GSTRIDE + kk * 8 + tg]);
                a[tt2][1] = f2tf32(as[(r0 + 8) * GSTRIDE + kk * 8 + tg]);
                a[tt2][2] = f2tf32(as[r0 * GSTRIDE + kk * 8 + tg + 4]);
                a[tt2][3] = f2tf32(as[(r0 + 8) * GSTRIDE + kk * 8 + tg + 4]);
            }
#pragma unroll
            for (int j = 0; j < 4; j++) {
                unsigned b0 = f2tf32(ws[(nb + j * 8 + gl) * GSTRIDE + kk * 8 + tg]);
                unsigned b1 = f2tf32(ws[(nb + j * 8 + gl) * GSTRIDE + kk * 8 + tg + 4]);
                mma8(acc[0][j], a[0], b0, b1);
                mma8(acc[1][j], a[1], b0, b1);
            }
        }
    }
#pragma unroll
    for (int tt2 = 0; tt2 < 2; tt2++)
#pragma unroll
        for (int j = 0; j < 4; j++) {
            int r0 = mb + tt2 * 16 + gl;
            int col = n0 + nb + j * 8 + 2 * tg;
            float b0v = 0.f, b1v = 0.f;
            if (bias) { b0v = bias[col]; b1v = bias[col + 1]; }
            C[(size_t)r0 * ldc + col]           = acc[tt2][j][0] + b0v;
            C[(size_t)r0 * ldc + col + 1]       = acc[tt2][j][1] + b1v;
            C[(size_t)(r0 + 8) * ldc + col]     = acc[tt2][j][2] + b0v;
            C[(size_t)(r0 + 8) * ldc + col + 1] = acc[tt2][j][3] + b1v;
        }
}

__global__ void __launch_bounds__(128, 2) qkv_gemm(
    const float* __restrict__ A,
    const float* __restrict__ qw, const float* __restrict__ qb,
    const float* __restrict__ kw, const float* __restrict__ kb,
    const float* __restrict__ vw, const float* __restrict__ vb)
{
    extern __shared__ float gsm[];
    int nt  = blockIdx.x % 96;
    int ksl = blockIdx.x / 96;
    int kbase = ksl * 1024;
    float* Cp = g_qkvp + (size_t)ksl * QKVP_SL;
    if (nt < 64)
        gemm_body(A, qw, (ksl == 0) ? qb : nullptr, Cp, NQKV, nt * 64, kbase, gsm);
    else if (nt < 80)
        gemm_body(A, kw, (ksl == 0) ? kb : nullptr, Cp + 4096, NQKV, (nt - 64) * 64, kbase, gsm);
    else
        gemm_body(A, vw, (ksl == 0) ? vb : nullptr, Cp + 5120, NQKV, (nt - 80) * 64, kbase, gsm);
}

__global__ void __launch_bounds__(128, 2) o_gemm(const float* __restrict__ ow)
{
    extern __shared__ float gsm[];
    int nt  = blockIdx.x % 64;
    int ksl = blockIdx.x / 64;
    gemm_body(g_ao, ow, nullptr, g_op + (size_t)ksl * OP_SL, HID, nt * 64, ksl * 1024, gsm);
}

__global__ void __launch_bounds__(256) o_reduce(float* __restrict__ out)
{
    int idx = blockIdx.x * 256 + threadIdx.x;
    out[idx] = g_op[idx] + g_op[OP_SL + idx] + g_op[2 * OP_SL + idx] + g_op[3 * OP_SL + idx];
}

// ---------------- RoPE + scatter (positions[b][s] == b*S+s) ----------------
__device__ __forceinline__ float qkvp_sum(int m, int col) {
    return g_qkvp[(size_t)m * NQKV + col]
         + g_qkvp[QKVP_SL + (size_t)m * NQKV + col]
         + g_qkvp[2 * QKVP_SL + (size_t)m * NQKV + col]
         + g_qkvp[3 * QKVP_SL + (size_t)m * NQKV + col];
}

__global__ void __launch_bounds__(256) rope_scatter(
    float* __restrict__ knew, float* __restrict__ vnew)
{
    int idx = blockIdx.x * 256 + threadIdx.x;
    const float NEG_LOG2_BASE_OVER_HALF = -13.287712379549449f / 64.f;
    if (idx < 131072) {                       // Q
        int d0 = idx & 63;
        int h  = (idx >> 6) & 31;
        int m  = idx >> 11;
        int b = m >> 2, s = m & 3;
        float ang = (float)m * exp2f((float)d0 * NEG_LOG2_BASE_OVER_HALF);
        float c = cosf(ang), sn = sinf(ang);
        float x1 = qkvp_sum(m, h * 128 + d0);
        float x2 = qkvp_sum(m, h * 128 + d0 + 64);
        int g = h >> 2, r = h & 3, row = r * 4 + s;
        int base = ((b * 8 + g) * 16 + row) * 128;
        g_q[base + d0]      = (x1 * c - x2 * sn) * SCALE;
        g_q[base + d0 + 64] = (x2 * c + x1 * sn) * SCALE;
    } else if (idx < 163840) {                // K
        int j = idx - 131072;
        int d0 = j & 63;
        int kv = (j >> 6) & 7;
        int m  = j >> 9;
        int b = m >> 2, s = m & 3;
        float ang = (float)m * exp2f((float)d0 * NEG_LOG2_BASE_OVER_HALF);
        float c = cosf(ang), sn = sinf(ang);
        float x1 = qkvp_sum(m, 4096 + kv * 128 + d0);
        float x2 = qkvp_sum(m, 4096 + kv * 128 + d0 + 64);
        int base = ((b * 8 + kv) * 4 + s) * 128;
        knew[base + d0]      = x1 * c - x2 * sn;
        knew[base + d0 + 64] = x2 * c + x1 * sn;
    } else if (idx < 229376) {                // V
        int j = idx - 163840;
        int d  = j & 127;
        int kv = (j >> 7) & 7;
        int m  = j >> 10;
        int b = m >> 2, s = m & 3;
        vnew[((b * 8 + kv) * 4 + s) * 128 + d] = qkvp_sum(m, 5120 + kv * 128 + d);
    }
}

// ================= Attention (restructured: PV split by D across warps) =============
// grid 1024: bg = blk>>3, sub = blk&7 -> keys [sub*512, +512), 16 tiles of 32.
// QK: warp w computes keys w*8..w*8+7.  P published via smem with block-wide max.
// PV: warp w computes D columns w*32..w*32+31 over all 32 keys.
#define NT 16
#define KROWK 132
#define VROWV 136
#define SMK_STAGE (32*KROWK)
#define SMV_STAGE (32*VROWV)
#define PS_OFF   (2*SMK_STAGE + 2*SMV_STAGE)      // 17152
#define REDM_OFF (PS_OFF + 16*36)                 // 17728
#define REDL_OFF (REDM_OFF + 64)                  // 17792
#define SMEM_ATTN ((REDL_OFF + 64) * sizeof(float))   // 71424 B

__global__ void __launch_bounds__(128, 3) attn2(
    const float* __restrict__ kc, const float* __restrict__ vc,
    const float* __restrict__ knew, const float* __restrict__ vnew)
{
    extern __shared__ float sm[];
    float* Ks   = sm;                      // [2][32][132]
    float* Vs   = sm + 2 * SMK_STAGE;      // [2][32][136]
    float* Ps   = sm + PS_OFF;             // [16][36]
    float* redm = sm + REDM_OFF;           // [4][16]
    float* redl = sm + REDL_OFF;           // [4][16]

    const int tid = threadIdx.x, wid = tid >> 5, lane = tid & 31;
    const int gl = lane >> 2, tg = lane & 3;
    const int bg = blockIdx.x >> 3, sub = blockIdx.x & 7;
    const int kbase = sub * 512;

    const float* kcb = kc + (size_t)bg * TT * DD;
    const float* vcb = vc + (size_t)bg * TT * DD;
    const float* knb = knew + (size_t)bg * SS * DD;
    const float* vnb = vnew + (size_t)bg * SS * DD;

    // Q fragments in registers (loop-invariant)
    const float* q = g_q + (size_t)bg * 2048;
    unsigned aq[16][4];
#pragma unroll
    for (int kk = 0; kk < 16; kk++) {
        aq[kk][0] = f2tf32(q[gl * 128 + kk * 8 + tg]);
        aq[kk][1] = f2tf32(q[(gl + 8) * 128 + kk * 8 + tg]);
        aq[kk][2] = f2tf32(q[gl * 128 + kk * 8 + tg + 4]);
        aq[kk][3] = f2tf32(q[(gl + 8) * 128 + kk * 8 + tg + 4]);
    }

    float acc[4][4];   // rows gl/gl+8, D cols wid*32 + nt*8 + {2tg,2tg+1}
#pragma unroll
    for (int nt = 0; nt < 4; nt++)
#pragma unroll
        for (int c = 0; c < 4; c++) acc[nt][c] = 0.f;
    float m0 = -1e30f, m1 = -1e30f, l0 = 0.f, l1 = 0.f;

    auto stageK = [&](int buf, int tile) {
        int key0 = kbase + tile * 32;
        float* kd = Ks + buf * SMK_STAGE;
        if (key0 + 32 <= T0) {
            const char* ksrc = (const char*)(kcb + (size_t)key0 * DD);
#pragma unroll
            for (int i = 0; i < 8; i++) {
                int f = tid + i * 128;
                int row = f >> 5, c4 = (f & 31) * 4;
                cpa16(&kd[row * KROWK + c4], ksrc + (size_t)f * 16);
            }
        } else {
#pragma unroll
            for (int i = 0; i < 8; i++) {
                int f = tid + i * 128;
                int row = f >> 5, c4 = (f & 31) * 4;
                int t = key0 + row;
                const float* ks = (t < T0) ? (kcb + (size_t)t * DD + c4) : (knb + (size_t)(t - T0) * DD + c4);
                cpa16(&kd[row * KROWK + c4], ks);
            }
        }
        CPA_COMMIT();
    };
    auto stageV = [&](int buf, int tile) {
        int key0 = kbase + tile * 32;
        float* vd = Vs + buf * SMV_STAGE;
        if (key0 + 32 <= T0) {
            const char* vsrc = (const char*)(vcb + (size_t)key0 * DD);
#pragma unroll
            for (int i = 0; i < 8; i++) {
                int f = tid + i * 128;
                int row = f >> 5, c4 = (f & 31) * 4;
                cpa16(&vd[row * VROWV + c4], vsrc + (size_t)f * 16);
            }
        } else {
#pragma unroll
            for (int i = 0; i < 8; i++) {
                int f = tid + i * 128;
                int row = f >> 5, c4 = (f & 31) * 4;
                int t = key0 + row;
                const float* vs = (t < T0) ? (vcb + (size_t)t * DD + c4) : (vnb + (size_t)(t - T0) * DD + c4);
                cpa16(&vd[row * VROWV + c4], vs);
            }
        }
        CPA_COMMIT();
    };

    stageK(0, 0);
    stageV(0, 0);

#pragma unroll 1
    for (int tile = 0; tile < NT; tile++) {
        int buf = tile & 1;
        asm volatile("cp.async.wait_group 1;" ::: "memory");  // K_t ready
        __syncthreads();                                      // buf + Ps/red reuse safe
        if (tile + 1 < NT) {
            stageK(buf ^ 1, tile + 1);
            stageV(buf ^ 1, tile + 1);
        }

        // ---- QK^T for this warp's 8 keys (dual chains) ----
        const float* KT = Ks + buf * SMK_STAGE + wid * 8 * KROWK;
        float csA[4] = {0.f, 0.f, 0.f, 0.f};
        float csB[4] = {0.f, 0.f, 0.f, 0.f};
#pragma unroll
        for (int kk = 0; kk < 16; kk += 2) {
            unsigned b0 = f2tf32(KT[gl * KROWK + kk * 8 + tg]);
            unsigned b1 = f2tf32(KT[gl * KROWK + kk * 8 + tg + 4]);
            mma8(csA, aq[kk], b0, b1);
            unsigned c0 = f2tf32(KT[gl * KROWK + kk * 8 + 8 + tg]);
            unsigned c1 = f2tf32(KT[gl * KROWK + kk * 8 + 8 + tg + 4]);
            mma8(csB, aq[kk + 1], c0, c1);
        }
        float cs[4];
#pragma unroll
        for (int c = 0; c < 4; c++) cs[c] = csA[c] + csB[c];

        // ---- warp-local row max over its 8 keys ----
        float cm0 = fmaxf(cs[0], cs[1]);
        cm0 = fmaxf(cm0, __shfl_xor_sync(0xffffffffu, cm0, 1));
        cm0 = fmaxf(cm0, __shfl_xor_sync(0xffffffffu, cm0, 2));
        float cm1 = fmaxf(cs[2], cs[3]);
        cm1 = fmaxf(cm1, __shfl_xor_sync(0xffffffffu, cm1, 1));
        cm1 = fmaxf(cm1, __shfl_xor_sync(0xffffffffu, cm1, 2));
        if (tg == 0) {
            redm[wid * 16 + gl]     = cm0;
            redm[wid * 16 + gl + 8] = cm1;
        }
        __syncthreads();
        // ---- block row max ----
        float t0 = fmaxf(fmaxf(redm[gl], redm[16 + gl]), fmaxf(redm[32 + gl], redm[48 + gl]));
        float t1 = fmaxf(fmaxf(redm[gl + 8], redm[24 + gl]), fmaxf(redm[40 + gl], redm[56 + gl]));
        float nm0 = fmaxf(m0, t0), nm1 = fmaxf(m1, t1);
        float f0 = __expf(m0 - nm0), f1 = __expf(m1 - nm1);
        float p0 = __expf(cs[0] - nm0), p1 = __expf(cs[1] - nm0);
        float p2 = __expf(cs[2] - nm1), p3 = __expf(cs[3] - nm1);
        float rs0 = p0 + p1, rs1 = p2 + p3;
        rs0 += __shfl_xor_sync(0xffffffffu, rs0, 1);
        rs0 += __shfl_xor_sync(0xffffffffu, rs0, 2);
        rs1 += __shfl_xor_sync(0xffffffffu, rs1, 1);
        rs1 += __shfl_xor_sync(0xffffffffu, rs1, 2);
        if (tg == 0) {
            redl[wid * 16 + gl]     = rs0;
            redl[wid * 16 + gl + 8] = rs1;
        }
        // publish P(16x32): warp w owns key cols w*8 + {2tg, 2tg+1}
        Ps[gl * 36 + wid * 8 + 2 * tg]           = p0;
        Ps[gl * 36 + wid * 8 + 2 * tg + 1]       = p1;
        Ps[(gl + 8) * 36 + wid * 8 + 2 * tg]     = p2;
        Ps[(gl + 8) * 36 + wid * 8 + 2 * tg + 1] = p3;

        if (tile + 1 < NT) asm volatile("cp.async.wait_group 2;" ::: "memory");  // V_t ready
        else               asm volatile("cp.async.wait_group 0;" ::: "memory");
        __syncthreads();

        // ---- update l, rescale acc ----
        l0 = l0 * f0 + (redl[gl] + redl[16 + gl] + redl[32 + gl] + redl[48 + gl]);
        l1 = l1 * f1 + (redl[gl + 8] + redl[24 + gl] + redl[40 + gl] + redl[56 + gl]);
        m0 = nm0; m1 = nm1;
#pragma unroll
        for (int nt = 0; nt < 4; nt++) {
            acc[nt][0] *= f0; acc[nt][1] *= f0;
            acc[nt][2] *= f1; acc[nt][3] *= f1;
        }

        // ---- PV: P(16x32) * V(32 x [wid*32..wid*32+31]) ----
        const float* VT = Vs + buf * SMV_STAGE;
#pragma unroll
        for (int k8 = 0; k8 < 4; k8++) {
            unsigned pa[4];
            pa[0] = f2tf32(Ps[gl * 36 + k8 * 8 + tg]);
            pa[1] = f2tf32(Ps[(gl + 8) * 36 + k8 * 8 + tg]);
            pa[2] = f2tf32(Ps[gl * 36 + k8 * 8 + tg + 4]);
            pa[3] = f2tf32(Ps[(gl + 8) * 36 + k8 * 8 + tg + 4]);
            const float* vr0 = VT + (k8 * 8 + tg) * VROWV;
            const float* vr1 = VT + (k8 * 8 + tg + 4) * VROWV;
#pragma unroll
            for (int nt = 0; nt < 4; nt++) {
                int col = wid * 32 + nt * 8 + gl;
                unsigned b0 = f2tf32(vr0[col]);
                unsigned b1 = f2tf32(vr1[col]);
                mma8(acc[nt], pa, b0, b1);
            }
        }
    }

    // ---- write block partial: warp owns disjoint D cols, no merge needed ----
    const int p = bg * NSPLIT + sub;
    float* po = g_part_acc + (size_t)p * 2048;
#pragma unroll
    for (int nt = 0; nt < 4; nt++) {
        int col = wid * 32 + nt * 8 + 2 * tg;
        po[gl * 128 + col]           = acc[nt][0];
        po[gl * 128 + col + 1]       = acc[nt][1];
        po[(gl + 8) * 128 + col]     = acc[nt][2];
        po[(gl + 8) * 128 + col + 1] = acc[nt][3];
    }
    if (wid == 0 && tg == 0) {
        g_part_m[p * 16 + gl]     = m0;
        g_part_m[p * 16 + gl + 8] = m1;
        g_part_l[p * 16 + gl]     = l0;
        g_part_l[p * 16 + gl + 8] = l1;
    }
}

// ---------------- combine: one thread per output element, 8 partials ----------------
__global__ void __launch_bounds__(256) combine_kernel()
{
    int idx = blockIdx.x * 256 + threadIdx.x;   // 0..262143
    int bg  = idx >> 11;
    int row = (idx >> 7) & 15;
    int d   = idx & 127;
    float M = -1e30f;
#pragma unroll
    for (int sp = 0; sp < NSPLIT; sp++)
        M = fmaxf(M, g_part_m[(bg * NSPLIT + sp) * 16 + row]);
    float sum = 0.f, L = 0.f;
#pragma unroll
    for (int sp = 0; sp < NSPLIT; sp++) {
        int pp = bg * NSPLIT + sp;
        float w = __expf(g_part_m[pp * 16 + row] - M);
        L   += g_part_l[pp * 16 + row] * w;
        sum += g_part_acc[(size_t)pp * 2048 + row * 128 + d] * w;
    }
    float o = sum / L;
    int b = bg >> 3, g = bg & 7;
    int h = g * 4 + (row >> 2);
    int s = row & 3;
    int m = b * 4 + s;
    g_ao[(size_t)m * 4096 + h * 128 + d] = o;
}

// ---------------- launch ----------------
extern "C" void kernel_launch(void* const* d_in, const int* in_sizes, int n_in,
                              void* d_out, int out_size)
{
    const float* hs = (const float*)d_in[0];
    const float* kc = (const float*)d_in[2];
    const float* vc = (const float*)d_in[3];
    const float* qw = (const float*)d_in[5];
    const float* qb = (const float*)d_in[6];
    const float* kw = (const float*)d_in[7];
    const float* kb = (const float*)d_in[8];
    const float* vw = (const float*)d_in[9];
    const float* vb = (const float*)d_in[10];
    const float* ow = (const float*)d_in[11];

    float* out  = (float*)d_out;
    float* knew = out + KNEW_OFF;
    float* vnew = out + VNEW_OFF;

    cudaFuncSetAttribute(attn2, cudaFuncAttributeMaxDynamicSharedMemorySize, (int)SMEM_ATTN);
    cudaFuncSetAttribute(qkv_gemm, cudaFuncAttributeMaxDynamicSharedMemorySize, (int)GEMM_SMEM);
    cudaFuncSetAttribute(o_gemm, cudaFuncAttributeMaxDynamicSharedMemorySize, (int)GEMM_SMEM);

    qkv_gemm<<<384, 128, GEMM_SMEM>>>(hs, qw, qb, kw, kb, vw, vb);
    rope_scatter<<<896, 256>>>(knew, vnew);
    attn2<<<1024, 128, SMEM_ATTN>>>(kc, vc, knew, vnew);
    combine_kernel<<<1024, 256>>>();
    o_gemm<<<256, 128, GEMM_SMEM>>>(ow);
    o_reduce<<<1024, 256>>>(out);
}